// round 16
// baseline (speedup 1.0000x reference)
#include <cuda_runtime.h>
#include <cuda_bf16.h>
#include <cstdint>

#define BB 64
#define TT 2048
#define JJ 256
#define DD 200
#define DPAD 256
#define TR 64            // t-rows per CTA (2 CTAs/SM)
#define NTH 256
#define RSB 432          // bf16 row stride bytes: odd 16B groups -> ldsm conflict-free
#define JCH 32           // j rows per u chunk (8 chunks, single buffer)

typedef unsigned long long ull;

// ---------------- device scratch ----------------
__device__ __align__(256) __nv_bfloat16 g_u_hi[BB * JJ * DPAD];
__device__ __align__(256) __nv_bfloat16 g_u_lo[BB * JJ * DPAD];
__device__ float g_alpha_u[BB * JJ];
__device__ float g_m[BB * TT];
__device__ float g_q2c[BB * DD];
__device__ float g_part[BB * 16 * DD];
__device__ float g_bias[1];

// ---------------- helpers ----------------
__device__ __forceinline__ uint32_t sm32(const void* p) { return (uint32_t)__cvta_generic_to_shared(p); }
__device__ __forceinline__ uint32_t bfpack(float a, float b) {
    __nv_bfloat162 t = __floats2bfloat162_rn(a, b);
    return *reinterpret_cast<uint32_t*>(&t);
}
__device__ __forceinline__ ull pack4bf(float a, float b, float c, float d) {
    return (ull)bfpack(a, b) | ((ull)bfpack(c, d) << 32);
}

__device__ __forceinline__ void ldsm4(uint32_t& r0, uint32_t& r1, uint32_t& r2, uint32_t& r3, uint32_t a) {
    asm volatile("ldmatrix.sync.aligned.m8n8.x4.shared.b16 {%0,%1,%2,%3}, [%4];"
                 : "=r"(r0), "=r"(r1), "=r"(r2), "=r"(r3) : "r"(a));
}
__device__ __forceinline__ void ldsm4t(uint32_t& r0, uint32_t& r1, uint32_t& r2, uint32_t& r3, uint32_t a) {
    asm volatile("ldmatrix.sync.aligned.m8n8.x4.trans.shared.b16 {%0,%1,%2,%3}, [%4];"
                 : "=r"(r0), "=r"(r1), "=r"(r2), "=r"(r3) : "r"(a));
}
__device__ __forceinline__ void ldsm2t(uint32_t& r0, uint32_t& r1, uint32_t a) {
    asm volatile("ldmatrix.sync.aligned.m8n8.x2.trans.shared.b16 {%0,%1}, [%2];"
                 : "=r"(r0), "=r"(r1) : "r"(a));
}
__device__ __forceinline__ void mma16816(float* c, uint32_t a0, uint32_t a1, uint32_t a2, uint32_t a3,
                                         uint32_t b0, uint32_t b1) {
    asm volatile("mma.sync.aligned.m16n8k16.row.col.f32.bf16.bf16.f32 "
                 "{%0,%1,%2,%3}, {%4,%5,%6,%7}, {%8,%9}, {%0,%1,%2,%3};"
                 : "+f"(c[0]), "+f"(c[1]), "+f"(c[2]), "+f"(c[3])
                 : "r"(a0), "r"(a1), "r"(a2), "r"(a3), "r"(b0), "r"(b1));
}

// ---------------- smem layout (bytes), per CTA (x2 resident) ----------------
#define OFF_HWH   0                      // 64 x 432
#define OFF_HWL   27648
#define OFF_U     55296                  // single buffer: 32 rows hi + lo plane
#define UPLANE    13824
#define OFF_PB    82944                  // 4 blocks x (16 rows hi + lo) x 80B
#define PBBLK     2560
#define OFF_AU    93184                  // 256 floats
#define OFF_AH    94208                  // 64 floats
#define OFF_MXP   94464                  // 2 x 64 floats
#define OFF_SMP   94976                  // 2 x 64 floats
#define OFF_INV   95488                  // 64 floats
#define SMEM_BYTES 95744

// ---------------- prep: fused split-convert + alpha_u (one pass over u) ----------------
__global__ __launch_bounds__(256)
void u_prep_kernel(const float* __restrict__ u, const float* __restrict__ w_u, int row_off) {
    const int row  = row_off + blockIdx.x * 8 + (threadIdx.x >> 5);
    const int lane = threadIdx.x & 31;
    const float* ur = u + (size_t)row * DD;
    __nv_bfloat16* uh = g_u_hi + (size_t)row * DPAD;
    __nv_bfloat16* ul = g_u_lo + (size_t)row * DPAD;
    float s = 0.f;
    #pragma unroll
    for (int k = 0; k < 8; ++k) {
        int c = lane + k * 32;
        float x = (c < DD) ? ur[c] : 0.f;
        __nv_bfloat16 hb = __float2bfloat16_rn(x);
        uh[c] = hb;
        ul[c] = __float2bfloat16_rn(x - __bfloat162float(hb));
        if (c < DD) s += x * w_u[c];
    }
    #pragma unroll
    for (int o = 16; o > 0; o >>= 1) s += __shfl_xor_sync(0xffffffffu, s, o);
    if (lane == 0) g_alpha_u[row] = s;
}

__global__ void bias_kernel(const float* __restrict__ b_h, const float* __restrict__ b_u,
                            const float* __restrict__ b_hu) {
    if (threadIdx.x == 0) g_bias[0] = b_h[0] + b_u[0] + b_hu[0];
}

// ---------------- main fused kernel ----------------
extern __shared__ char smx[];

// register-staged u chunk: LDG early (latency hidden behind QK/PV), STS after post-PV sync
__device__ __forceinline__ void ldg_chunk(const __nv_bfloat16* uh, const __nv_bfloat16* ul,
                                          uint4* Rh, uint4* Rl, int tid) {
    #pragma unroll
    for (int k = 0; k < 4; ++k) {
        int i = tid + k * NTH;
        if (i < JCH * 26) {
            int r = i / 26, c = i % 26;
            Rh[k] = __ldg(reinterpret_cast<const uint4*>(uh + (size_t)r * DPAD + c * 8));
            Rl[k] = __ldg(reinterpret_cast<const uint4*>(ul + (size_t)r * DPAD + c * 8));
        }
    }
}
__device__ __forceinline__ void sts_chunk(char* smb, const uint4* Rh, const uint4* Rl, int tid) {
    #pragma unroll
    for (int k = 0; k < 4; ++k) {
        int i = tid + k * NTH;
        if (i < JCH * 26) {
            int r = i / 26, c = i % 26;
            *reinterpret_cast<uint4*>(smb + OFF_U + r * RSB + c * 16) = Rh[k];
            *reinterpret_cast<uint4*>(smb + OFF_U + UPLANE + r * RSB + c * 16) = Rl[k];
        }
    }
}

__global__ __launch_bounds__(NTH, 2)
void bidaf_main_kernel(const float* __restrict__ h, const float* __restrict__ w_h,
                       const float* __restrict__ w_hu, float* __restrict__ g) {
    char* smb = smx;
    const int tid  = threadIdx.x;
    const int lane = tid & 31;
    const int w    = tid >> 5;          // 0..7
    const int rb   = w >> 1;            // 16-row block 0..3
    const int q    = w & 1;             // j-half in QK, d-half in PV
    const int m0   = rb * 16;
    const int bb   = blockIdx.y;
    const int t0   = blockIdx.x * TR;

    float* au_s  = reinterpret_cast<float*>(smb + OFF_AU);
    float* ah_s  = reinterpret_cast<float*>(smb + OFF_AH);
    float* mxp   = reinterpret_cast<float*>(smb + OFF_MXP);
    float* smp   = reinterpret_cast<float*>(smb + OFF_SMP);
    float* inv_s = reinterpret_cast<float*>(smb + OFF_INV);

    const __nv_bfloat16* ubase_h = g_u_hi + (size_t)bb * JJ * DPAD;
    const __nv_bfloat16* ubase_l = g_u_lo + (size_t)bb * JJ * DPAD;

    // prefetch chunk 0 into registers (latency overlaps hw staging + alpha_h)
    uint4 Rh[4], Rl[4];
    ldg_chunk(ubase_h, ubase_l, Rh, Rl, tid);

    const float* hbase = h + ((size_t)bb * TT + t0) * DD;

    // ---- stage hw = h*w_hu split hi/lo: 64 rows x 50 quads + ZERO pad quads 50,51 ----
    {
        int r = tid >> 2, hf = tid & 3;
        const float4* hr4 = reinterpret_cast<const float4*>(hbase + (size_t)r * DD);
        char* HWH = smb + OFF_HWH;
        char* HWL = smb + OFF_HWL;
        #pragma unroll
        for (int s = 0; s < 13; ++s) {
            int qd = hf * 13 + s;
            if (qd < 50) {
                float4 hv = __ldg(hr4 + qd);
                float4 wv = __ldg(reinterpret_cast<const float4*>(w_hu) + qd);
                float x0 = hv.x * wv.x, x1 = hv.y * wv.y, x2 = hv.z * wv.z, x3 = hv.w * wv.w;
                float h0 = __bfloat162float(__float2bfloat16_rn(x0));
                float h1 = __bfloat162float(__float2bfloat16_rn(x1));
                float h2 = __bfloat162float(__float2bfloat16_rn(x2));
                float h3 = __bfloat162float(__float2bfloat16_rn(x3));
                *reinterpret_cast<ull*>(HWH + r * RSB + qd * 8) = pack4bf(h0, h1, h2, h3);
                *reinterpret_cast<ull*>(HWL + r * RSB + qd * 8) = pack4bf(x0 - h0, x1 - h1, x2 - h2, x3 - h3);
            } else {                     // qd = 50,51 -> bytes 400..415 read by ldsm k=12: zero
                *reinterpret_cast<ull*>(HWH + r * RSB + qd * 8) = 0ull;
                *reinterpret_cast<ull*>(HWL + r * RSB + qd * 8) = 0ull;
            }
        }
    }

    au_s[tid] = g_alpha_u[bb * JJ + tid];

    // ---- alpha_h: 8 rows per warp ----
    #pragma unroll
    for (int k = 0; k < 8; ++k) {
        int r = w * 8 + k;
        const float* hr = hbase + (size_t)r * DD;
        float s = 0.f;
        for (int c = lane; c < DD; c += 32) s += hr[c] * w_h[c];
        #pragma unroll
        for (int o = 16; o > 0; o >>= 1) s += __shfl_xor_sync(0xffffffffu, s, o);
        if (lane == 0) ah_s[r] = s;
    }

    // write chunk 0 to smem (published by loop-top sync)
    sts_chunk(smb, Rh, Rl, tid);

    const int t  = lane & 3;
    const int gg = lane >> 2;

    const uint32_t afrag = (uint32_t)((lane & 15) * RSB + (lane >> 4) * 16);
    const uint32_t qkb   = (uint32_t)(((lane & 7) + ((lane & 16) >> 1)) * RSB + ((lane >> 3) & 1) * 16);
    const uint32_t hwhi  = sm32(smb) + OFF_HWH + (uint32_t)(m0 * RSB) + afrag;
    const uint32_t hwlo  = hwhi + 27648;
    const uint32_t pbW   = sm32(smb) + OFF_PB + (uint32_t)(rb * PBBLK);
    const uint32_t pbA   = pbW + (uint32_t)((lane & 15) * 80 + (lane >> 4) * 16);
    const uint32_t ub    = sm32(smb) + OFF_U;
    const int pair_bar   = rb + 1;       // named barrier id 1..4, 64 threads (this pair)

    const int NT = q ? 12 : 13;          // PV d-tiles owned
    float C[13][4];
    #pragma unroll
    for (int n = 0; n < 13; ++n) { C[n][0] = C[n][1] = C[n][2] = C[n][3] = 0.f; }
    float mxg = -3.4e38f, mx8 = -3.4e38f, sumg = 0.f, sum8 = 0.f;
    float ahg = 0.f, ah8 = 0.f;

    #pragma unroll 1
    for (int jc = 0; jc < 8; ++jc) {
        __syncthreads();                 // chunk jc (STS'd last iter / prologue) visible
        // prefetch chunk jc+1 into registers: ~2600 cyc of QK/PV hide the LDG latency
        if (jc < 7)
            ldg_chunk(ubase_h + (size_t)(jc + 1) * JCH * DPAD,
                      ubase_l + (size_t)(jc + 1) * JCH * DPAD, Rh, Rl, tid);
        if (jc == 0) {
            const float bias = g_bias[0];
            ahg = ah_s[m0 + gg] + bias;
            ah8 = ah_s[m0 + 8 + gg] + bias;
        }

        // ---- QK: S[16 x 16] for this warp's j-half ----
        float S[2][4];
        S[0][0] = S[0][1] = S[0][2] = S[0][3] = 0.f;
        S[1][0] = S[1][1] = S[1][2] = S[1][3] = 0.f;
        {
            const uint32_t bqh = ub + (uint32_t)(q * 16 * RSB) + qkb;
            const uint32_t bql = bqh + UPLANE;
            #pragma unroll 2              // overlap next k's ldsm with this k's MMA chain
            for (int k = 0; k < 13; ++k) {
                uint32_t A0, A1, A2, A3, L0, L1, L2, L3;
                uint32_t B0, B1, B2, B3, M0, M1, M2, M3;
                ldsm4(A0, A1, A2, A3, hwhi + k * 32);
                ldsm4(L0, L1, L2, L3, hwlo + k * 32);
                ldsm4(B0, B1, B2, B3, bqh + k * 32);
                ldsm4(M0, M1, M2, M3, bql + k * 32);
                mma16816(S[0], A0, A1, A2, A3, B0, B1);
                mma16816(S[1], A0, A1, A2, A3, B2, B3);
                mma16816(S[0], A0, A1, A2, A3, M0, M1);
                mma16816(S[1], A0, A1, A2, A3, M2, M3);
                mma16816(S[0], L0, L1, L2, L3, B0, B1);
                mma16816(S[1], L0, L1, L2, L3, B2, B3);
            }
        }

        // ---- exp + write P frags (hi/lo) to pair-shared pbuf ----
        #pragma unroll
        for (int tile = 0; tile < 2; ++tile) {
            int jl = q * 16 + tile * 8 + 2 * t;
            float2 au2 = *reinterpret_cast<const float2*>(&au_s[jc * JCH + jl]);
            float s0 = S[tile][0] + ahg + au2.x;
            float s1 = S[tile][1] + ahg + au2.y;
            float s2 = S[tile][2] + ah8 + au2.x;
            float s3 = S[tile][3] + ah8 + au2.y;
            mxg = fmaxf(mxg, fmaxf(s0, s1));
            mx8 = fmaxf(mx8, fmaxf(s2, s3));
            float e0 = __expf(s0), e1 = __expf(s1), e2 = __expf(s2), e3 = __expf(s3);
            sumg += e0 + e1; sum8 += e2 + e3;
            float p0 = __bfloat162float(__float2bfloat16_rn(e0));
            float p1 = __bfloat162float(__float2bfloat16_rn(e1));
            float p2 = __bfloat162float(__float2bfloat16_rn(e2));
            float p3 = __bfloat162float(__float2bfloat16_rn(e3));
            uint32_t col = (uint32_t)(q * 32 + tile * 16 + t * 4);
            uint32_t rhi = pbW + (uint32_t)(gg * 80) + col;
            asm volatile("st.shared.b32 [%0], %1;" :: "r"(rhi),        "r"(bfpack(p0, p1)));
            asm volatile("st.shared.b32 [%0], %1;" :: "r"(rhi + 640),  "r"(bfpack(p2, p3)));
            asm volatile("st.shared.b32 [%0], %1;" :: "r"(rhi + 1280), "r"(bfpack(e0 - p0, e1 - p1)));
            asm volatile("st.shared.b32 [%0], %1;" :: "r"(rhi + 1920), "r"(bfpack(e2 - p2, e3 - p3)));
        }
        // pair-local barrier: only the 2 warps of this 16-row block exchange P
        asm volatile("bar.sync %0, 64;" :: "r"(pair_bar) : "memory");

        // ---- PV: C[16 x d-half] += P[16 x 32] * U[32 x d-half] ----
        const uint32_t pvb = ub + afrag + (uint32_t)(q ? 208 : 0);
        #pragma unroll
        for (int s = 0; s < 2; ++s) {
            uint32_t a0, a1, a2, a3, l0, l1, l2, l3;
            ldsm4(a0, a1, a2, a3, pbA + s * 32);
            ldsm4(l0, l1, l2, l3, pbA + 1280 + s * 32);
            uint32_t bh = pvb + (uint32_t)(s * 16 * RSB);
            uint32_t bl = bh + UPLANE;
            #pragma unroll
            for (int dp = 0; dp < 6; ++dp) {
                uint32_t B0, B1, B2, B3, M0, M1, M2, M3;
                ldsm4t(B0, B1, B2, B3, bh + dp * 32);
                ldsm4t(M0, M1, M2, M3, bl + dp * 32);
                mma16816(C[2 * dp],     a0, a1, a2, a3, B0, B1);
                mma16816(C[2 * dp + 1], a0, a1, a2, a3, B2, B3);
                mma16816(C[2 * dp],     a0, a1, a2, a3, M0, M1);
                mma16816(C[2 * dp + 1], a0, a1, a2, a3, M2, M3);
                mma16816(C[2 * dp],     l0, l1, l2, l3, B0, B1);
                mma16816(C[2 * dp + 1], l0, l1, l2, l3, B2, B3);
            }
            if (q == 0) {                // tile 12 (cols 96..103)
                uint32_t B0, B1, M0, M1;
                ldsm2t(B0, B1, bh + 192);
                ldsm2t(M0, M1, bl + 192);
                mma16816(C[12], a0, a1, a2, a3, B0, B1);
                mma16816(C[12], a0, a1, a2, a3, M0, M1);
                mma16816(C[12], l0, l1, l2, l3, B0, B1);
            }
        }
        __syncthreads();                 // all reads of u buffer + pbuf done
        if (jc < 7) sts_chunk(smb, Rh, Rl, tid);   // write prefetched chunk jc+1
    }

    // ---- combine pair partials (max/sum over j-halves) ----
    mxg = fmaxf(mxg, __shfl_xor_sync(0xffffffffu, mxg, 1));
    mxg = fmaxf(mxg, __shfl_xor_sync(0xffffffffu, mxg, 2));
    mx8 = fmaxf(mx8, __shfl_xor_sync(0xffffffffu, mx8, 1));
    mx8 = fmaxf(mx8, __shfl_xor_sync(0xffffffffu, mx8, 2));
    sumg += __shfl_xor_sync(0xffffffffu, sumg, 1);
    sumg += __shfl_xor_sync(0xffffffffu, sumg, 2);
    sum8 += __shfl_xor_sync(0xffffffffu, sum8, 1);
    sum8 += __shfl_xor_sync(0xffffffffu, sum8, 2);
    if (t == 0) {
        mxp[q * 64 + m0 + gg]     = mxg;
        mxp[q * 64 + m0 + 8 + gg] = mx8;
        smp[q * 64 + m0 + gg]     = sumg;
        smp[q * 64 + m0 + 8 + gg] = sum8;
    }
    __syncthreads();
    if (tid < TR) {
        g_m[bb * TT + t0 + tid] = fmaxf(mxp[tid], mxp[64 + tid]);
        inv_s[tid] = 1.0f / (smp[tid] + smp[64 + tid]);
    }
    __syncthreads();

    // ---- epilogue: this warp writes its d-half of g slots 0..2 ----
    const float ivg = inv_s[m0 + gg];
    const float iv8 = inv_s[m0 + 8 + gg];
    float* g0 = g + ((size_t)bb * TT + t0 + m0 + gg) * 800;
    float* g8 = g + ((size_t)bb * TT + t0 + m0 + 8 + gg) * 800;
    const float* h0p = hbase + (size_t)(m0 + gg) * DD;
    const float* h8p = hbase + (size_t)(m0 + 8 + gg) * DD;
    const int cb0 = q ? 104 : 0;
    #pragma unroll
    for (int nt = 0; nt < 13; ++nt) {
        if (nt < NT) {
            int col = cb0 + nt * 8 + 2 * t;
            float2 hv0 = *reinterpret_cast<const float2*>(h0p + col);
            float2 hv8 = *reinterpret_cast<const float2*>(h8p + col);
            float c0 = C[nt][0] * ivg, c1 = C[nt][1] * ivg;
            float c2 = C[nt][2] * iv8, c3 = C[nt][3] * iv8;
            *reinterpret_cast<float2*>(g0 + col)       = hv0;
            *reinterpret_cast<float2*>(g0 + 200 + col) = make_float2(c0, c1);
            *reinterpret_cast<float2*>(g0 + 400 + col) = make_float2(hv0.x * c0, hv0.y * c1);
            *reinterpret_cast<float2*>(g8 + col)       = hv8;
            *reinterpret_cast<float2*>(g8 + 200 + col) = make_float2(c2, c3);
            *reinterpret_cast<float2*>(g8 + 400 + col) = make_float2(hv8.x * c2, hv8.y * c3);
        }
    }
}

// ---------------- tail kernels ----------------
__global__ __launch_bounds__(256)
void beta_kernel() {
    __shared__ float red[8];
    const int b = blockIdx.x, tid = threadIdx.x;
    const int lane = tid & 31, wid = tid >> 5;
    float lm = -3.4e38f;
    float vals[8];
    #pragma unroll
    for (int k = 0; k < 8; ++k) {
        vals[k] = g_m[b * TT + tid + k * 256];
        lm = fmaxf(lm, vals[k]);
    }
    #pragma unroll
    for (int o = 16; o > 0; o >>= 1) lm = fmaxf(lm, __shfl_xor_sync(0xffffffffu, lm, o));
    if (lane == 0) red[wid] = lm;
    __syncthreads();
    float bm = red[0];
    #pragma unroll
    for (int i = 1; i < 8; ++i) bm = fmaxf(bm, red[i]);
    __syncthreads();
    float ls = 0.f;
    #pragma unroll
    for (int k = 0; k < 8; ++k) { vals[k] = __expf(vals[k] - bm); ls += vals[k]; }
    #pragma unroll
    for (int o = 16; o > 0; o >>= 1) ls += __shfl_xor_sync(0xffffffffu, ls, o);
    if (lane == 0) red[wid] = ls;
    __syncthreads();
    float bs = 0.f;
    #pragma unroll
    for (int i = 0; i < 8; ++i) bs += red[i];
    const float inv = 1.0f / bs;
    #pragma unroll
    for (int k = 0; k < 8; ++k) g_m[b * TT + tid + k * 256] = vals[k] * inv;
}

__global__ __launch_bounds__(256)
void q2c_part_kernel(const float* __restrict__ h) {
    const int p = blockIdx.x, b = blockIdx.y, tid = threadIdx.x;   // 16 parts x 128 t
    if (tid < DD) {
        const float* hb = h + ((size_t)b * TT + p * 128) * DD + tid;
        const float* bt = &g_m[b * TT + p * 128];
        float a0 = 0.f, a1 = 0.f, a2 = 0.f, a3 = 0.f;
        float a4 = 0.f, a5 = 0.f, a6 = 0.f, a7 = 0.f;
        #pragma unroll 2
        for (int tt = 0; tt < 128; tt += 8) {
            a0 += bt[tt]     * hb[(size_t)tt * DD];
            a1 += bt[tt + 1] * hb[(size_t)(tt + 1) * DD];
            a2 += bt[tt + 2] * hb[(size_t)(tt + 2) * DD];
            a3 += bt[tt + 3] * hb[(size_t)(tt + 3) * DD];
            a4 += bt[tt + 4] * hb[(size_t)(tt + 4) * DD];
            a5 += bt[tt + 5] * hb[(size_t)(tt + 5) * DD];
            a6 += bt[tt + 6] * hb[(size_t)(tt + 6) * DD];
            a7 += bt[tt + 7] * hb[(size_t)(tt + 7) * DD];
        }
        g_part[(b * 16 + p) * DD + tid] = ((a0 + a1) + (a2 + a3)) + ((a4 + a5) + (a6 + a7));
    }
}

__global__ void q2c_reduce_kernel() {
    int idx = blockIdx.x * 256 + threadIdx.x;
    if (idx < BB * DD) {
        int b = idx / DD, d = idx % DD;
        float s = 0.f;
        #pragma unroll
        for (int p = 0; p < 16; ++p) s += g_part[(b * 16 + p) * DD + d];
        g_q2c[idx] = s;
    }
}

__global__ void g3_kernel(const float* __restrict__ h, float* __restrict__ g) {
    int base = (blockIdx.x * 256 + threadIdx.x) * 2;   // 2 float4 per thread
    #pragma unroll
    for (int u2 = 0; u2 < 2; ++u2) {
        int idx = base + u2;
        int tl  = idx / 50;
        int c   = idx % 50;
        int b   = tl >> 11;
        float4 hv = reinterpret_cast<const float4*>(h)[idx];
        float4 qv = *reinterpret_cast<const float4*>(&g_q2c[b * DD + 4 * c]);
        float4 p; p.x = hv.x * qv.x; p.y = hv.y * qv.y; p.z = hv.z * qv.z; p.w = hv.w * qv.w;
        reinterpret_cast<float4*>(g)[(size_t)tl * 200 + 150 + c] = p;
    }
}

// ---------------------------------------------------------------------------
extern "C" void kernel_launch(void* const* d_in, const int* in_sizes, int n_in,
                              void* d_out, int out_size) {
    const float* h    = (const float*)d_in[0];
    const float* u    = (const float*)d_in[1];
    const float* w_h  = (const float*)d_in[2];
    const float* b_h  = (const float*)d_in[3];
    const float* w_u  = (const float*)d_in[4];
    const float* b_u  = (const float*)d_in[5];
    const float* w_hu = (const float*)d_in[6];
    const float* b_hu = (const float*)d_in[7];
    float* g = (float*)d_out;

    cudaFuncSetAttribute(bidaf_main_kernel, cudaFuncAttributeMaxDynamicSharedMemorySize, SMEM_BYTES);

    // launches #1-#3 (main = #4, the ncu capture slot)
    u_prep_kernel<<<(BB * JJ) / 16, 256>>>(u, w_u, 0);            // rows 0..8191
    u_prep_kernel<<<(BB * JJ) / 16, 256>>>(u, w_u, BB * JJ / 2);  // rows 8192..16383
    bias_kernel<<<1, 32>>>(b_h, b_u, b_hu);

    dim3 gridC(TT / TR, BB);
    bidaf_main_kernel<<<gridC, NTH, SMEM_BYTES>>>(h, w_h, w_hu, g);

    beta_kernel<<<BB, 256>>>();
    dim3 gridP(16, BB);
    q2c_part_kernel<<<gridP, 256>>>(h);
    q2c_reduce_kernel<<<(BB * DD + 255) / 256, 256>>>();
    g3_kernel<<<(BB * TT * 50) / 512, 256>>>(h, g);
}

// round 17
// speedup vs baseline: 1.0633x; 1.0633x over previous
#include <cuda_runtime.h>
#include <cuda_bf16.h>
#include <cstdint>

#define BB 64
#define TT 2048
#define JJ 256
#define DD 200
#define DPAD 256
#define TR 64            // t-rows per CTA (2 CTAs/SM)
#define NTH 256
#define RSB 432          // bf16 row stride bytes: odd 16B groups -> ldsm conflict-free
#define JCH 32           // j rows per u chunk (8 chunks, single buffer)

typedef unsigned long long ull;

// ---------------- device scratch ----------------
__device__ __align__(256) __nv_bfloat16 g_u_hi[BB * JJ * DPAD];
__device__ __align__(256) __nv_bfloat16 g_u_lo[BB * JJ * DPAD];
__device__ float g_alpha_u[BB * JJ];
__device__ float g_m[BB * TT];
__device__ float g_q2c[BB * DD];
__device__ float g_part[BB * 16 * DD];
__device__ float g_bias[1];

// ---------------- helpers ----------------
__device__ __forceinline__ uint32_t sm32(const void* p) { return (uint32_t)__cvta_generic_to_shared(p); }
__device__ __forceinline__ uint32_t bfpack(float a, float b) {
    __nv_bfloat162 t = __floats2bfloat162_rn(a, b);
    return *reinterpret_cast<uint32_t*>(&t);
}
__device__ __forceinline__ ull pack4bf(float a, float b, float c, float d) {
    return (ull)bfpack(a, b) | ((ull)bfpack(c, d) << 32);
}
__device__ __forceinline__ void cp16(uint32_t dst, const void* src) {
    asm volatile("cp.async.cg.shared.global [%0], [%1], 16;" :: "r"(dst), "l"(src));
}
__device__ __forceinline__ void cp_commit() { asm volatile("cp.async.commit_group;"); }
__device__ __forceinline__ void cp_wait0()  { asm volatile("cp.async.wait_group 0;"); }

__device__ __forceinline__ void ldsm4(uint32_t& r0, uint32_t& r1, uint32_t& r2, uint32_t& r3, uint32_t a) {
    asm volatile("ldmatrix.sync.aligned.m8n8.x4.shared.b16 {%0,%1,%2,%3}, [%4];"
                 : "=r"(r0), "=r"(r1), "=r"(r2), "=r"(r3) : "r"(a));
}
__device__ __forceinline__ void ldsm4t(uint32_t& r0, uint32_t& r1, uint32_t& r2, uint32_t& r3, uint32_t a) {
    asm volatile("ldmatrix.sync.aligned.m8n8.x4.trans.shared.b16 {%0,%1,%2,%3}, [%4];"
                 : "=r"(r0), "=r"(r1), "=r"(r2), "=r"(r3) : "r"(a));
}
__device__ __forceinline__ void ldsm2t(uint32_t& r0, uint32_t& r1, uint32_t a) {
    asm volatile("ldmatrix.sync.aligned.m8n8.x2.trans.shared.b16 {%0,%1}, [%2];"
                 : "=r"(r0), "=r"(r1) : "r"(a));
}
__device__ __forceinline__ void mma16816(float* c, uint32_t a0, uint32_t a1, uint32_t a2, uint32_t a3,
                                         uint32_t b0, uint32_t b1) {
    asm volatile("mma.sync.aligned.m16n8k16.row.col.f32.bf16.bf16.f32 "
                 "{%0,%1,%2,%3}, {%4,%5,%6,%7}, {%8,%9}, {%0,%1,%2,%3};"
                 : "+f"(c[0]), "+f"(c[1]), "+f"(c[2]), "+f"(c[3])
                 : "r"(a0), "r"(a1), "r"(a2), "r"(a3), "r"(b0), "r"(b1));
}

// ---------------- smem layout (bytes), per CTA (x2 resident) ----------------
#define OFF_HWH   0                      // 64 x 432
#define OFF_HWL   27648
#define OFF_U     55296                  // single buffer: 32 rows hi + lo plane
#define UPLANE    13824
#define OFF_PB    82944                  // 4 blocks x (16 rows hi + lo) x 80B
#define PBBLK     2560
#define OFF_AU    93184                  // 256 floats
#define OFF_AH    94208                  // 64 floats
#define OFF_MXP   94464                  // 2 x 64 floats
#define OFF_SMP   94976                  // 2 x 64 floats
#define OFF_INV   95488                  // 64 floats
#define SMEM_BYTES 95744

// ---------------- prep: fused split-convert + alpha_u (one pass over u) ----------------
__global__ __launch_bounds__(256)
void u_prep_kernel(const float* __restrict__ u, const float* __restrict__ w_u, int row_off) {
    const int row  = row_off + blockIdx.x * 8 + (threadIdx.x >> 5);
    const int lane = threadIdx.x & 31;
    const float* ur = u + (size_t)row * DD;
    __nv_bfloat16* uh = g_u_hi + (size_t)row * DPAD;
    __nv_bfloat16* ul = g_u_lo + (size_t)row * DPAD;
    float s = 0.f;
    #pragma unroll
    for (int k = 0; k < 8; ++k) {
        int c = lane + k * 32;
        float x = (c < DD) ? ur[c] : 0.f;
        __nv_bfloat16 hb = __float2bfloat16_rn(x);
        uh[c] = hb;
        ul[c] = __float2bfloat16_rn(x - __bfloat162float(hb));
        if (c < DD) s += x * w_u[c];
    }
    #pragma unroll
    for (int o = 16; o > 0; o >>= 1) s += __shfl_xor_sync(0xffffffffu, s, o);
    if (lane == 0) g_alpha_u[row] = s;
}

__global__ void bias_kernel(const float* __restrict__ b_h, const float* __restrict__ b_u,
                            const float* __restrict__ b_hu) {
    if (threadIdx.x == 0) g_bias[0] = b_h[0] + b_u[0] + b_hu[0];
}

// ---------------- main fused kernel ----------------
extern __shared__ char smx[];

__device__ __forceinline__ void stage_u(char* smb, int b, int jc, int tid) {
    uint32_t dhi = sm32(smb) + OFF_U;
    uint32_t dlo = dhi + UPLANE;
    const __nv_bfloat16* shi = g_u_hi + ((size_t)b * JJ + jc * JCH) * DPAD;
    const __nv_bfloat16* slo = g_u_lo + ((size_t)b * JJ + jc * JCH) * DPAD;
    // 32 rows x 26 quads(16B) per plane (quad 25 = cols 200..207, zeros via DPAD pad)
    #pragma unroll
    for (int i = tid; i < JCH * 26; i += NTH) {
        int r = i / 26, c = i % 26;
        uint32_t d = (uint32_t)(r * RSB + c * 16);
        cp16(dhi + d, shi + (size_t)r * DPAD + c * 8);
        cp16(dlo + d, slo + (size_t)r * DPAD + c * 8);
    }
    cp_commit();
}

__global__ __launch_bounds__(NTH, 2)
void bidaf_main_kernel(const float* __restrict__ h, const float* __restrict__ w_h,
                       const float* __restrict__ w_hu, float* __restrict__ g) {
    char* smb = smx;
    const int tid  = threadIdx.x;
    const int lane = tid & 31;
    const int w    = tid >> 5;          // 0..7
    const int rb   = w >> 1;            // 16-row block 0..3
    const int q    = w & 1;             // j-half in QK, d-half in PV
    const int m0   = rb * 16;
    const int bb   = blockIdx.y;
    const int t0   = blockIdx.x * TR;

    float* au_s  = reinterpret_cast<float*>(smb + OFF_AU);
    float* ah_s  = reinterpret_cast<float*>(smb + OFF_AH);
    float* mxp   = reinterpret_cast<float*>(smb + OFF_MXP);
    float* smp   = reinterpret_cast<float*>(smb + OFF_SMP);
    float* inv_s = reinterpret_cast<float*>(smb + OFF_INV);

    // prefetch u chunk 0 (overlaps hw staging + alpha_h)
    stage_u(smb, bb, 0, tid);

    const float* hbase = h + ((size_t)bb * TT + t0) * DD;

    // ---- stage hw = h*w_hu split hi/lo: 64 rows x 50 quads + ZERO pad quads 50,51 ----
    {
        int r = tid >> 2, hf = tid & 3;
        const float4* hr4 = reinterpret_cast<const float4*>(hbase + (size_t)r * DD);
        char* HWH = smb + OFF_HWH;
        char* HWL = smb + OFF_HWL;
        #pragma unroll
        for (int s = 0; s < 13; ++s) {
            int qd = hf * 13 + s;
            if (qd < 50) {
                float4 hv = __ldg(hr4 + qd);
                float4 wv = __ldg(reinterpret_cast<const float4*>(w_hu) + qd);
                float x0 = hv.x * wv.x, x1 = hv.y * wv.y, x2 = hv.z * wv.z, x3 = hv.w * wv.w;
                float h0 = __bfloat162float(__float2bfloat16_rn(x0));
                float h1 = __bfloat162float(__float2bfloat16_rn(x1));
                float h2 = __bfloat162float(__float2bfloat16_rn(x2));
                float h3 = __bfloat162float(__float2bfloat16_rn(x3));
                *reinterpret_cast<ull*>(HWH + r * RSB + qd * 8) = pack4bf(h0, h1, h2, h3);
                *reinterpret_cast<ull*>(HWL + r * RSB + qd * 8) = pack4bf(x0 - h0, x1 - h1, x2 - h2, x3 - h3);
            } else {                     // qd = 50,51 -> bytes 400..415 read by ldsm k=12: zero
                *reinterpret_cast<ull*>(HWH + r * RSB + qd * 8) = 0ull;
                *reinterpret_cast<ull*>(HWL + r * RSB + qd * 8) = 0ull;
            }
        }
    }

    au_s[tid] = g_alpha_u[bb * JJ + tid];

    // ---- alpha_h: 8 rows per warp ----
    #pragma unroll
    for (int k = 0; k < 8; ++k) {
        int r = w * 8 + k;
        const float* hr = hbase + (size_t)r * DD;
        float s = 0.f;
        for (int c = lane; c < DD; c += 32) s += hr[c] * w_h[c];
        #pragma unroll
        for (int o = 16; o > 0; o >>= 1) s += __shfl_xor_sync(0xffffffffu, s, o);
        if (lane == 0) ah_s[r] = s;
    }

    const int t  = lane & 3;
    const int gg = lane >> 2;

    const uint32_t afrag = (uint32_t)((lane & 15) * RSB + (lane >> 4) * 16);
    const uint32_t qkb   = (uint32_t)(((lane & 7) + ((lane & 16) >> 1)) * RSB + ((lane >> 3) & 1) * 16);
    const uint32_t hwhi  = sm32(smb) + OFF_HWH + (uint32_t)(m0 * RSB) + afrag;
    const uint32_t hwlo  = hwhi + 27648;
    const uint32_t pbW   = sm32(smb) + OFF_PB + (uint32_t)(rb * PBBLK);
    const uint32_t pbA   = pbW + (uint32_t)((lane & 15) * 80 + (lane >> 4) * 16);
    const uint32_t ub    = sm32(smb) + OFF_U;
    const int pair_bar   = rb + 1;       // named barrier id 1..4, 64 threads (this pair)

    const int NT = q ? 12 : 13;          // PV d-tiles owned
    float C[13][4];
    #pragma unroll
    for (int n = 0; n < 13; ++n) { C[n][0] = C[n][1] = C[n][2] = C[n][3] = 0.f; }
    float mxg = -3.4e38f, mx8 = -3.4e38f, sumg = 0.f, sum8 = 0.f;
    float ahg = 0.f, ah8 = 0.f;

    #pragma unroll 1
    for (int jc = 0; jc < 8; ++jc) {
        cp_wait0();
        __syncthreads();                 // chunk jc visible to all
        if (jc == 0) {
            const float bias = g_bias[0];
            ahg = ah_s[m0 + gg] + bias;
            ah8 = ah_s[m0 + 8 + gg] + bias;
        }

        // ---- QK: S[16 x 16] for this warp's j-half ----
        float S[2][4];
        S[0][0] = S[0][1] = S[0][2] = S[0][3] = 0.f;
        S[1][0] = S[1][1] = S[1][2] = S[1][3] = 0.f;
        {
            const uint32_t bqh = ub + (uint32_t)(q * 16 * RSB) + qkb;
            const uint32_t bql = bqh + UPLANE;
            #pragma unroll 2              // overlap next k's ldsm with this k's MMA chain
            for (int k = 0; k < 13; ++k) {
                uint32_t A0, A1, A2, A3, L0, L1, L2, L3;
                uint32_t B0, B1, B2, B3, M0, M1, M2, M3;
                ldsm4(A0, A1, A2, A3, hwhi + k * 32);
                ldsm4(L0, L1, L2, L3, hwlo + k * 32);
                ldsm4(B0, B1, B2, B3, bqh + k * 32);
                ldsm4(M0, M1, M2, M3, bql + k * 32);
                mma16816(S[0], A0, A1, A2, A3, B0, B1);
                mma16816(S[1], A0, A1, A2, A3, B2, B3);
                mma16816(S[0], A0, A1, A2, A3, M0, M1);
                mma16816(S[1], A0, A1, A2, A3, M2, M3);
                mma16816(S[0], L0, L1, L2, L3, B0, B1);
                mma16816(S[1], L0, L1, L2, L3, B2, B3);
            }
        }

        // ---- exp + P frags: own A-frags kept in registers (C->A identity),
        //      hi/lo also written to pair pbuf for the partner warp ----
        uint32_t ownH[4], ownL[4];
        #pragma unroll
        for (int tile = 0; tile < 2; ++tile) {
            int jl = q * 16 + tile * 8 + 2 * t;
            float2 au2 = *reinterpret_cast<const float2*>(&au_s[jc * JCH + jl]);
            float s0 = S[tile][0] + ahg + au2.x;
            float s1 = S[tile][1] + ahg + au2.y;
            float s2 = S[tile][2] + ah8 + au2.x;
            float s3 = S[tile][3] + ah8 + au2.y;
            mxg = fmaxf(mxg, fmaxf(s0, s1));
            mx8 = fmaxf(mx8, fmaxf(s2, s3));
            float e0 = __expf(s0), e1 = __expf(s1), e2 = __expf(s2), e3 = __expf(s3);
            sumg += e0 + e1; sum8 += e2 + e3;
            float p0 = __bfloat162float(__float2bfloat16_rn(e0));
            float p1 = __bfloat162float(__float2bfloat16_rn(e1));
            float p2 = __bfloat162float(__float2bfloat16_rn(e2));
            float p3 = __bfloat162float(__float2bfloat16_rn(e3));
            uint32_t hi01 = bfpack(p0, p1);
            uint32_t hi23 = bfpack(p2, p3);
            uint32_t lo01 = bfpack(e0 - p0, e1 - p1);
            uint32_t lo23 = bfpack(e2 - p2, e3 - p3);
            // A-frag identity: a0=tile(row gg), a1=tile(row gg+8); tile0 -> [0],[1], tile1 -> [2],[3]
            ownH[tile * 2 + 0] = hi01;  ownH[tile * 2 + 1] = hi23;
            ownL[tile * 2 + 0] = lo01;  ownL[tile * 2 + 1] = lo23;
            uint32_t col = (uint32_t)(q * 32 + tile * 16 + t * 4);
            uint32_t rhi = pbW + (uint32_t)(gg * 80) + col;
            asm volatile("st.shared.b32 [%0], %1;" :: "r"(rhi),        "r"(hi01));
            asm volatile("st.shared.b32 [%0], %1;" :: "r"(rhi + 640),  "r"(hi23));
            asm volatile("st.shared.b32 [%0], %1;" :: "r"(rhi + 1280), "r"(lo01));
            asm volatile("st.shared.b32 [%0], %1;" :: "r"(rhi + 1920), "r"(lo23));
        }
        // pair-local barrier: only the 2 warps of this 16-row block exchange P
        asm volatile("bar.sync %0, 64;" :: "r"(pair_bar) : "memory");

        // ---- PV: C[16 x d-half] += P[16 x 32] * U[32 x d-half] ----
        // s == q tile: A-frags from own registers; partner tile: ldsm from pbuf
        const uint32_t pvb = ub + afrag + (uint32_t)(q ? 208 : 0);
        #pragma unroll
        for (int s = 0; s < 2; ++s) {
            uint32_t a0, a1, a2, a3, l0, l1, l2, l3;
            if (s == q) {
                a0 = ownH[0]; a1 = ownH[1]; a2 = ownH[2]; a3 = ownH[3];
                l0 = ownL[0]; l1 = ownL[1]; l2 = ownL[2]; l3 = ownL[3];
            } else {
                ldsm4(a0, a1, a2, a3, pbA + s * 32);
                ldsm4(l0, l1, l2, l3, pbA + 1280 + s * 32);
            }
            uint32_t bh = pvb + (uint32_t)(s * 16 * RSB);
            uint32_t bl = bh + UPLANE;
            #pragma unroll
            for (int dp = 0; dp < 6; ++dp) {
                uint32_t B0, B1, B2, B3, M0, M1, M2, M3;
                ldsm4t(B0, B1, B2, B3, bh + dp * 32);
                ldsm4t(M0, M1, M2, M3, bl + dp * 32);
                mma16816(C[2 * dp],     a0, a1, a2, a3, B0, B1);
                mma16816(C[2 * dp + 1], a0, a1, a2, a3, B2, B3);
                mma16816(C[2 * dp],     a0, a1, a2, a3, M0, M1);
                mma16816(C[2 * dp + 1], a0, a1, a2, a3, M2, M3);
                mma16816(C[2 * dp],     l0, l1, l2, l3, B0, B1);
                mma16816(C[2 * dp + 1], l0, l1, l2, l3, B2, B3);
            }
            if (q == 0) {                // tile 12 (cols 96..103)
                uint32_t B0, B1, M0, M1;
                ldsm2t(B0, B1, bh + 192);
                ldsm2t(M0, M1, bl + 192);
                mma16816(C[12], a0, a1, a2, a3, B0, B1);
                mma16816(C[12], a0, a1, a2, a3, M0, M1);
                mma16816(C[12], l0, l1, l2, l3, B0, B1);
            }
        }
        __syncthreads();                 // all reads of u buffer + pbuf done
        if (jc < 7) stage_u(smb, bb, jc + 1, tid);   // refill single buffer
    }

    // ---- combine pair partials (max/sum over j-halves) ----
    mxg = fmaxf(mxg, __shfl_xor_sync(0xffffffffu, mxg, 1));
    mxg = fmaxf(mxg, __shfl_xor_sync(0xffffffffu, mxg, 2));
    mx8 = fmaxf(mx8, __shfl_xor_sync(0xffffffffu, mx8, 1));
    mx8 = fmaxf(mx8, __shfl_xor_sync(0xffffffffu, mx8, 2));
    sumg += __shfl_xor_sync(0xffffffffu, sumg, 1);
    sumg += __shfl_xor_sync(0xffffffffu, sumg, 2);
    sum8 += __shfl_xor_sync(0xffffffffu, sum8, 1);
    sum8 += __shfl_xor_sync(0xffffffffu, sum8, 2);
    if (t == 0) {
        mxp[q * 64 + m0 + gg]     = mxg;
        mxp[q * 64 + m0 + 8 + gg] = mx8;
        smp[q * 64 + m0 + gg]     = sumg;
        smp[q * 64 + m0 + 8 + gg] = sum8;
    }
    __syncthreads();
    if (tid < TR) {
        g_m[bb * TT + t0 + tid] = fmaxf(mxp[tid], mxp[64 + tid]);
        inv_s[tid] = 1.0f / (smp[tid] + smp[64 + tid]);
    }
    __syncthreads();

    // ---- epilogue: this warp writes its d-half of g slots 0..2 ----
    const float ivg = inv_s[m0 + gg];
    const float iv8 = inv_s[m0 + 8 + gg];
    float* g0 = g + ((size_t)bb * TT + t0 + m0 + gg) * 800;
    float* g8 = g + ((size_t)bb * TT + t0 + m0 + 8 + gg) * 800;
    const float* h0p = hbase + (size_t)(m0 + gg) * DD;
    const float* h8p = hbase + (size_t)(m0 + 8 + gg) * DD;
    const int cb0 = q ? 104 : 0;
    #pragma unroll
    for (int nt = 0; nt < 13; ++nt) {
        if (nt < NT) {
            int col = cb0 + nt * 8 + 2 * t;
            float2 hv0 = *reinterpret_cast<const float2*>(h0p + col);
            float2 hv8 = *reinterpret_cast<const float2*>(h8p + col);
            float c0 = C[nt][0] * ivg, c1 = C[nt][1] * ivg;
            float c2 = C[nt][2] * iv8, c3 = C[nt][3] * iv8;
            *reinterpret_cast<float2*>(g0 + col)       = hv0;
            *reinterpret_cast<float2*>(g0 + 200 + col) = make_float2(c0, c1);
            *reinterpret_cast<float2*>(g0 + 400 + col) = make_float2(hv0.x * c0, hv0.y * c1);
            *reinterpret_cast<float2*>(g8 + col)       = hv8;
            *reinterpret_cast<float2*>(g8 + 200 + col) = make_float2(c2, c3);
            *reinterpret_cast<float2*>(g8 + 400 + col) = make_float2(hv8.x * c2, hv8.y * c3);
        }
    }
}

// ---------------- tail kernels ----------------
__global__ __launch_bounds__(256)
void beta_kernel() {
    __shared__ float red[8];
    const int b = blockIdx.x, tid = threadIdx.x;
    const int lane = tid & 31, wid = tid >> 5;
    float lm = -3.4e38f;
    float vals[8];
    #pragma unroll
    for (int k = 0; k < 8; ++k) {
        vals[k] = g_m[b * TT + tid + k * 256];
        lm = fmaxf(lm, vals[k]);
    }
    #pragma unroll
    for (int o = 16; o > 0; o >>= 1) lm = fmaxf(lm, __shfl_xor_sync(0xffffffffu, lm, o));
    if (lane == 0) red[wid] = lm;
    __syncthreads();
    float bm = red[0];
    #pragma unroll
    for (int i = 1; i < 8; ++i) bm = fmaxf(bm, red[i]);
    __syncthreads();
    float ls = 0.f;
    #pragma unroll
    for (int k = 0; k < 8; ++k) { vals[k] = __expf(vals[k] - bm); ls += vals[k]; }
    #pragma unroll
    for (int o = 16; o > 0; o >>= 1) ls += __shfl_xor_sync(0xffffffffu, ls, o);
    if (lane == 0) red[wid] = ls;
    __syncthreads();
    float bs = 0.f;
    #pragma unroll
    for (int i = 0; i < 8; ++i) bs += red[i];
    const float inv = 1.0f / bs;
    #pragma unroll
    for (int k = 0; k < 8; ++k) g_m[b * TT + tid + k * 256] = vals[k] * inv;
}

__global__ __launch_bounds__(256)
void q2c_part_kernel(const float* __restrict__ h) {
    const int p = blockIdx.x, b = blockIdx.y, tid = threadIdx.x;   // 16 parts x 128 t
    if (tid < DD) {
        const float* hb = h + ((size_t)b * TT + p * 128) * DD + tid;
        const float* bt = &g_m[b * TT + p * 128];
        float a0 = 0.f, a1 = 0.f, a2 = 0.f, a3 = 0.f;
        float a4 = 0.f, a5 = 0.f, a6 = 0.f, a7 = 0.f;
        #pragma unroll 2
        for (int tt = 0; tt < 128; tt += 8) {
            a0 += bt[tt]     * hb[(size_t)tt * DD];
            a1 += bt[tt + 1] * hb[(size_t)(tt + 1) * DD];
            a2 += bt[tt + 2] * hb[(size_t)(tt + 2) * DD];
            a3 += bt[tt + 3] * hb[(size_t)(tt + 3) * DD];
            a4 += bt[tt + 4] * hb[(size_t)(tt + 4) * DD];
            a5 += bt[tt + 5] * hb[(size_t)(tt + 5) * DD];
            a6 += bt[tt + 6] * hb[(size_t)(tt + 6) * DD];
            a7 += bt[tt + 7] * hb[(size_t)(tt + 7) * DD];
        }
        g_part[(b * 16 + p) * DD + tid] = ((a0 + a1) + (a2 + a3)) + ((a4 + a5) + (a6 + a7));
    }
}

__global__ void q2c_reduce_kernel() {
    int idx = blockIdx.x * 256 + threadIdx.x;
    if (idx < BB * DD) {
        int b = idx / DD, d = idx % DD;
        float s = 0.f;
        #pragma unroll
        for (int p = 0; p < 16; ++p) s += g_part[(b * 16 + p) * DD + d];
        g_q2c[idx] = s;
    }
}

__global__ void g3_kernel(const float* __restrict__ h, float* __restrict__ g) {
    int base = (blockIdx.x * 256 + threadIdx.x) * 2;   // 2 float4 per thread
    #pragma unroll
    for (int u2 = 0; u2 < 2; ++u2) {
        int idx = base + u2;
        int tl  = idx / 50;
        int c   = idx % 50;
        int b   = tl >> 11;
        float4 hv = reinterpret_cast<const float4*>(h)[idx];
        float4 qv = *reinterpret_cast<const float4*>(&g_q2c[b * DD + 4 * c]);
        float4 p; p.x = hv.x * qv.x; p.y = hv.y * qv.y; p.z = hv.z * qv.z; p.w = hv.w * qv.w;
        reinterpret_cast<float4*>(g)[(size_t)tl * 200 + 150 + c] = p;
    }
}

// ---------------------------------------------------------------------------
extern "C" void kernel_launch(void* const* d_in, const int* in_sizes, int n_in,
                              void* d_out, int out_size) {
    const float* h    = (const float*)d_in[0];
    const float* u    = (const float*)d_in[1];
    const float* w_h  = (const float*)d_in[2];
    const float* b_h  = (const float*)d_in[3];
    const float* w_u  = (const float*)d_in[4];
    const float* b_u  = (const float*)d_in[5];
    const float* w_hu = (const float*)d_in[6];
    const float* b_hu = (const float*)d_in[7];
    float* g = (float*)d_out;

    cudaFuncSetAttribute(bidaf_main_kernel, cudaFuncAttributeMaxDynamicSharedMemorySize, SMEM_BYTES);

    // launches #1-#3 (main = #4, the ncu capture slot)
    u_prep_kernel<<<(BB * JJ) / 16, 256>>>(u, w_u, 0);            // rows 0..8191
    u_prep_kernel<<<(BB * JJ) / 16, 256>>>(u, w_u, BB * JJ / 2);  // rows 8192..16383
    bias_kernel<<<1, 32>>>(b_h, b_u, b_hu);

    dim3 gridC(TT / TR, BB);
    bidaf_main_kernel<<<gridC, NTH, SMEM_BYTES>>>(h, w_h, w_hu, g);

    beta_kernel<<<BB, 256>>>();
    dim3 gridP(16, BB);
    q2c_part_kernel<<<gridP, 256>>>(h);
    q2c_reduce_kernel<<<(BB * DD + 255) / 256, 256>>>();
    g3_kernel<<<(BB * TT * 50) / 512, 256>>>(h, g);
}